// round 13
// baseline (speedup 1.0000x reference)
#include <cuda_runtime.h>

#define Bn 4
#define Pn 8
#define Vn 2048
#define En 2048
#define Fn 4096
#define TILES 4
#define TPB 512              // 16 warps = 2 edge-halves x 8 chunk-lanes
#define CHAM_BLOCKS (Bn * Pn * TILES)   // 128
#define EMAX 2052
#define BIGF 3.402823466e38f

__device__ float g_part_sum[CHAM_BLOCKS];
__device__ float g_part_cnt[CHAM_BLOCKS];
__device__ unsigned int g_counter;   // never reset; +CHAM_BLOCKS per launch

// ---------------------------------------------------------------------------
// packed fp32x2 helpers (sm_103a FFMA2)
// ---------------------------------------------------------------------------
__device__ __forceinline__ unsigned long long bcast2(float v) {
    unsigned long long r;
    asm("mov.b64 %0, {%1, %1};" : "=l"(r) : "f"(v));
    return r;
}

// d2[k] = px*x2[k] + py*y2[k] + c2[k]  for k=0,1 ; fold into mins
__device__ __forceinline__ void edge2(float& m0, float& m1,
                                      unsigned long long pxx, unsigned long long pyy,
                                      unsigned long long x2, unsigned long long y2,
                                      unsigned long long c2)
{
    float d0, d1;
    asm("{\n\t"
        ".reg .b64 t;\n\t"
        "fma.rn.f32x2 t, %2, %3, %4;\n\t"
        "fma.rn.f32x2 t, %5, %6, t;\n\t"
        "mov.b64 {%0, %1}, t;\n\t"
        "}"
        : "=f"(d0), "=f"(d1)
        : "l"(pyy), "l"(y2), "l"(c2), "l"(pxx), "l"(x2));
    m0 = fminf(m0, d0);
    m1 = fminf(m1, d1);
}

// ---------------------------------------------------------------------------
// Blocks [0,128): chamfer — 512 verts compacted to masked-only; 16 warps =
// 2 edge-halves x 8 chunk-lanes; chunk loop keeps every warp on live slots.
// Blocks [128,132): volume. One block/SM, single wave.
// ---------------------------------------------------------------------------
__global__ void __launch_bounds__(TPB)
fused_kernel(const float* __restrict__ xs,
             const float* __restrict__ pm,
             const float* __restrict__ em,
             const int*   __restrict__ lens,
             const void*  __restrict__ bmask,
             const int*   __restrict__ faces,
             const float* __restrict__ tv,
             float* __restrict__ out)
{
    const int bx  = blockIdx.x;
    const int tid = threadIdx.x;

    // =========================== VOLUME BLOCKS ============================
    if (bx >= CHAM_BLOCKS) {
        __shared__ double sred[TPB];
        const int b = bx - CHAM_BLOCKS;
        const float* base = xs + (size_t)b * Vn * 3;
        double acc = 0.0;
        for (int f = tid; f < Fn; f += TPB) {
            const int* fi = faces + ((size_t)b * Fn + f) * 3;
            const float* a0 = base + (size_t)fi[0] * 3;
            const float* a1 = base + (size_t)fi[1] * 3;
            const float* a2 = base + (size_t)fi[2] * 3;
            const float v0x = a0[0], v0y = a0[1], v0z = a0[2];
            const float v1x = a1[0], v1y = a1[1], v1z = a1[2];
            const float v2x = a2[0], v2y = a2[1], v2z = a2[2];
            const float cx = v0y * v1z - v0z * v1y;
            const float cy = v0z * v1x - v0x * v1z;
            const float cz = v0x * v1y - v0y * v1x;
            acc += (double)((cx * v2x + cy * v2y + cz * v2z) * (1.0f / 6.0f));
        }
        sred[tid] = acc;
        __syncthreads();
        #pragma unroll
        for (int s = TPB / 2; s >= 1; s >>= 1) {
            if (tid < s) sred[tid] += sred[tid + s];
            __syncthreads();
        }
        if (tid == 0) {
            float vols = fabsf((float)sred[0]);
            float d = vols - tv[b];
            out[4 + b] = d * d;
        }
        return;
    }

    // =========================== CHAMFER BLOCKS ===========================
    __shared__ __align__(16) float s_c[EMAX];
    __shared__ __align__(16) float s_x[EMAX];
    __shared__ __align__(16) float s_y[EMAX];
    __shared__ short s_vidx[TPB];                  // compacted local vert ids
    __shared__ int   s_wofs[17];                   // warp prefix offsets
    __shared__ float s_e[2][TPB];                  // per-half per-slot mins (+pp)
    __shared__ float s_rs[TPB / 32];
    __shared__ int   s_last;

    const int tile   = bx & (TILES - 1);
    const int p      = (bx >> 2) & (Pn - 1);
    const int b      = bx >> 5;
    const int lane31 = tid & 31;
    const int wid    = tid >> 5;
    const int halfid = tid >> 8;                   // 0/1 edge half
    const int winh   = (tid & 255) >> 5;           // chunk lane (0..7)

    const int L    = lens[b * Pn + p];
    const int len4 = (L + 3) & ~3;
    const int S    = ((L >> 1) + 3) & ~3;          // 4-edge-aligned split point

    // ---- preload + transform edge table ----
    const float4* embase4 = (const float4*)(em + ((size_t)(b * Pn + p)) * En * 2);
    float2* c2p = (float2*)s_c;
    float2* x2p = (float2*)s_x;
    float2* y2p = (float2*)s_y;
    #pragma unroll
    for (int i = tid; i < En / 2; i += TPB) {
        float4 e4 = embase4[i];                 // ex0, ey0, ex1, ey1
        c2p[i] = make_float2(fmaf(e4.x, e4.x, e4.y * e4.y),
                             fmaf(e4.z, e4.z, e4.w * e4.w));
        x2p[i] = make_float2(-2.0f * e4.x, -2.0f * e4.z);
        y2p[i] = make_float2(-2.0f * e4.y, -2.0f * e4.w);
    }
    for (int i = L + tid; i < len4; i += TPB) {    // BIG pad -> tail-free loops
        s_c[i] = BIGF; s_x[i] = 0.0f; s_y[i] = 0.0f;
    }

    // ---- boundary_mask layout detection (first 4KB) ----
    unsigned int scan = 0;
    {
        const unsigned int* mw = (const unsigned int*)bmask;
        #pragma unroll
        for (int i = tid; i < 1024; i += TPB)
            scan |= (mw[i] & 0xFFFFFF00u);
    }
    const int mask_is_bytes = __syncthreads_or(scan != 0);  // also preload barrier

    // ---- deterministic compaction of this block's 512 verts (masked only) ----
    const int vbase = tile * TPB;                  // 512 verts per block
    const int midx0 = (b * Pn + p) * Vn + vbase + tid;
    bool m;
    if (mask_is_bytes) m = (((const unsigned char*)bmask)[midx0] != 0);
    else               m = (((const int*)bmask)[midx0] != 0);
    const unsigned int bal = __ballot_sync(0xffffffffu, m);
    if (lane31 == 0) s_wofs[wid + 1] = __popc(bal);
    __syncthreads();
    if (tid == 0) {
        s_wofs[0] = 0;
        #pragma unroll
        for (int i = 1; i <= 16; ++i) s_wofs[i] += s_wofs[i - 1];
    }
    __syncthreads();
    if (m) {
        const int pos = s_wofs[wid] + __popc(bal & ((1u << lane31) - 1u));
        s_vidx[pos] = (short)tid;                  // fixed tid order -> deterministic
    }
    const int NC = s_wofs[16];
    __syncthreads();

    // ---- edge range for this half ----
    const int i0 = halfid ? (S >> 2) : 0;
    const int i1 = halfid ? (len4 >> 2) : (S >> 2);
    const ulonglong2* pc  = (const ulonglong2*)s_c;
    const ulonglong2* pxv = (const ulonglong2*)s_x;
    const ulonglong2* pyv = (const ulonglong2*)s_y;
    const float* M = pm + p * 12;

    // ---- chunk loop: warp takes slot-chunks winh, winh+8, ... ----
    for (int c = winh; c * 32 < NC; c += 8) {
        const int slot = c * 32 + lane31;
        const bool live = (slot < NC);

        // projection for this slot's vertex (dummy 0s when dead)
        float x = 0.0f, y = 0.0f, z = 0.0f;
        if (live) {
            const int v = vbase + (int)s_vidx[slot];
            const float* xv = xs + ((size_t)b * Vn + v) * 3;
            x = xv[0]; y = xv[1]; z = xv[2];
        }
        const float q0 = M[0] * x + M[1] * y + M[2]  * z + M[3];
        const float q1 = M[4] * x + M[5] * y + M[6]  * z + M[7];
        const float q2 = M[8] * x + M[9] * y + M[10] * z + M[11];
        const float px = q0 / q2;
        const float py = q1 / q2;
        const float pp = fmaf(px, px, py * py);
        const unsigned long long pxx = bcast2(px);
        const unsigned long long pyy = bcast2(py);

        // edge loop: 4 edges per iteration, rotated prefetch
        float m0 = BIGF, m1 = BIGF, m2 = BIGF, m3 = BIGF;
        ulonglong2 c4 = pc[i0], x4 = pxv[i0], y4 = pyv[i0];
        #pragma unroll 2
        for (int i = i0 + 1; i < i1; ++i) {
            const ulonglong2 cn = pc[i];
            const ulonglong2 xn = pxv[i];
            const ulonglong2 yn = pyv[i];
            edge2(m0, m1, pxx, pyy, x4.x, y4.x, c4.x);
            edge2(m2, m3, pxx, pyy, x4.y, y4.y, c4.y);
            c4 = cn; x4 = xn; y4 = yn;
        }
        edge2(m0, m1, pxx, pyy, x4.x, y4.x, c4.x);
        edge2(m2, m3, pxx, pyy, x4.y, y4.y, c4.y);

        if (live)
            s_e[halfid][slot] = fminf(fminf(m0, m1), fminf(m2, m3)) + pp;
    }
    __syncthreads();

    // ---- combine halves by slot; weights are all 1, count = NC ----
    float cs = 0.0f;
    if (tid < NC) cs = fminf(s_e[0][tid], s_e[1][tid]);

    #pragma unroll
    for (int off = 16; off >= 1; off >>= 1)
        cs += __shfl_down_sync(0xffffffffu, cs, off);
    if (lane31 == 0) s_rs[wid] = cs;
    __syncthreads();

    if (tid == 0) {
        float ts = 0.0f;
        #pragma unroll
        for (int i = 0; i < TPB / 32; ++i) ts += s_rs[i];
        const int slotg = ((b * Pn + p) * TILES) + tile;
        g_part_sum[slotg] = ts;
        g_part_cnt[slotg] = (float)NC;
        __threadfence();
        unsigned int old = atomicAdd(&g_counter, 1u);
        s_last = (((old + 1u) & (CHAM_BLOCKS - 1u)) == 0u) ? 1 : 0;
    }
    __syncthreads();

    // ---- last block finalizes chamfer means ----
    if (s_last && tid < 32) {
        __threadfence();
        const int ln = tid;                      // ln = b*Pn + p
        float s = 0.0f, c = 0.0f;
        #pragma unroll
        for (int t = 0; t < TILES; ++t) {
            s += g_part_sum[ln * TILES + t];
            c += g_part_cnt[ln * TILES + t];
        }
        float ppj = s / fmaxf(c, 1.0f);
        #pragma unroll
        for (int off = 4; off >= 1; off >>= 1)
            ppj += __shfl_down_sync(0xffffffffu, ppj, off, 8);
        if ((ln & 7) == 0) out[ln >> 3] = ppj * (1.0f / Pn);
    }
}

// ---------------------------------------------------------------------------
extern "C" void kernel_launch(void* const* d_in, const int* in_sizes, int n_in,
                              void* d_out, int out_size)
{
    const float* xs    = (const float*)d_in[0];   // (4,2048,3)
    const float* pm    = (const float*)d_in[1];   // (8,3,4)
    const float* em    = (const float*)d_in[2];   // (4,8,2048,2)
    const int*   lens  = (const int*)  d_in[3];   // (4,8)
    const void*  bmask =               d_in[4];   // (4,8,2048) bool (auto-detected)
    const int*   faces = (const int*)  d_in[5];   // (4,4096,3)
    const float* tv    = (const float*)d_in[6];   // (4,)
    float* out = (float*)d_out;                   // [chamfer(4), vol_error(4)]

    fused_kernel<<<CHAM_BLOCKS + Bn, TPB>>>(xs, pm, em, lens, bmask, faces, tv, out);
}

// round 14
// speedup vs baseline: 1.2931x; 1.2931x over previous
#include <cuda_runtime.h>

#define Bn 4
#define Pn 8
#define Vn 2048
#define En 2048
#define Fn 4096
#define TILES 4
#define TPB 512              // 16 warps; items = (slot-chunk, edge-quarter)
#define CHAM_BLOCKS (Bn * Pn * TILES)   // 128
#define EMAX 2052
#define BIGF 3.402823466e38f

__device__ float g_part_sum[CHAM_BLOCKS];
__device__ float g_part_cnt[CHAM_BLOCKS];
__device__ unsigned int g_counter;   // never reset; +CHAM_BLOCKS per launch

// ---------------------------------------------------------------------------
// packed fp32x2 helpers (sm_103a FFMA2)
// ---------------------------------------------------------------------------
__device__ __forceinline__ unsigned long long bcast2(float v) {
    unsigned long long r;
    asm("mov.b64 %0, {%1, %1};" : "=l"(r) : "f"(v));
    return r;
}

// d2[k] = px*x2[k] + py*y2[k] + c2[k]  for k=0,1 ; fold into mins
__device__ __forceinline__ void edge2(float& m0, float& m1,
                                      unsigned long long pxx, unsigned long long pyy,
                                      unsigned long long x2, unsigned long long y2,
                                      unsigned long long c2)
{
    float d0, d1;
    asm("{\n\t"
        ".reg .b64 t;\n\t"
        "fma.rn.f32x2 t, %2, %3, %4;\n\t"
        "fma.rn.f32x2 t, %5, %6, t;\n\t"
        "mov.b64 {%0, %1}, t;\n\t"
        "}"
        : "=f"(d0), "=f"(d1)
        : "l"(pyy), "l"(y2), "l"(c2), "l"(pxx), "l"(x2));
    m0 = fminf(m0, d0);
    m1 = fminf(m1, d1);
}

// ---------------------------------------------------------------------------
// Blocks [0,128): chamfer — 512 verts compacted to masked-only; work items =
// (64-slot chunk) x (edge quarter) so ALL 16 warps stay active at VPT=2.
// Blocks [128,132): volume. One block/SM, single wave.
// ---------------------------------------------------------------------------
__global__ void __launch_bounds__(TPB)
fused_kernel(const float* __restrict__ xs,
             const float* __restrict__ pm,
             const float* __restrict__ em,
             const int*   __restrict__ lens,
             const void*  __restrict__ bmask,
             const int*   __restrict__ faces,
             const float* __restrict__ tv,
             float* __restrict__ out)
{
    const int bx  = blockIdx.x;
    const int tid = threadIdx.x;

    // =========================== VOLUME BLOCKS ============================
    if (bx >= CHAM_BLOCKS) {
        __shared__ double sred[TPB];
        const int b = bx - CHAM_BLOCKS;
        const float* base = xs + (size_t)b * Vn * 3;
        double acc = 0.0;
        for (int f = tid; f < Fn; f += TPB) {
            const int* fi = faces + ((size_t)b * Fn + f) * 3;
            const float* a0 = base + (size_t)fi[0] * 3;
            const float* a1 = base + (size_t)fi[1] * 3;
            const float* a2 = base + (size_t)fi[2] * 3;
            const float v0x = a0[0], v0y = a0[1], v0z = a0[2];
            const float v1x = a1[0], v1y = a1[1], v1z = a1[2];
            const float v2x = a2[0], v2y = a2[1], v2z = a2[2];
            const float cx = v0y * v1z - v0z * v1y;
            const float cy = v0z * v1x - v0x * v1z;
            const float cz = v0x * v1y - v0y * v1x;
            acc += (double)((cx * v2x + cy * v2y + cz * v2z) * (1.0f / 6.0f));
        }
        sred[tid] = acc;
        __syncthreads();
        #pragma unroll
        for (int s = TPB / 2; s >= 1; s >>= 1) {
            if (tid < s) sred[tid] += sred[tid + s];
            __syncthreads();
        }
        if (tid == 0) {
            float vols = fabsf((float)sred[0]);
            float d = vols - tv[b];
            out[4 + b] = d * d;
        }
        return;
    }

    // =========================== CHAMFER BLOCKS ===========================
    __shared__ __align__(16) float s_c[EMAX];
    __shared__ __align__(16) float s_x[EMAX];
    __shared__ __align__(16) float s_y[EMAX];
    __shared__ short s_vidx[TPB];                  // compacted local vert ids
    __shared__ int   s_wofs[17];                   // warp prefix offsets
    __shared__ float s_e[4][TPB];                  // per-quarter per-slot raw mins
    __shared__ float s_pp[TPB];                    // |p|^2 per slot
    __shared__ float s_rs[TPB / 32];
    __shared__ int   s_last;

    const int tile   = bx & (TILES - 1);
    const int p      = (bx >> 2) & (Pn - 1);
    const int b      = bx >> 5;
    const int lane31 = tid & 31;
    const int wid    = tid >> 5;

    const int L    = lens[b * Pn + p];
    const int len4 = (L + 3) & ~3;
    // 16B-aligned quarter boundaries
    int S[5];
    S[0] = 0;
    S[1] = ((L >> 2) + 3) & ~3;
    S[2] = ((L >> 1) + 3) & ~3;
    S[3] = (((3 * L) >> 2) + 3) & ~3;
    S[4] = len4;

    // ---- preload + transform edge table ----
    const float4* embase4 = (const float4*)(em + ((size_t)(b * Pn + p)) * En * 2);
    float2* c2p = (float2*)s_c;
    float2* x2p = (float2*)s_x;
    float2* y2p = (float2*)s_y;
    #pragma unroll
    for (int i = tid; i < En / 2; i += TPB) {
        float4 e4 = embase4[i];                 // ex0, ey0, ex1, ey1
        c2p[i] = make_float2(fmaf(e4.x, e4.x, e4.y * e4.y),
                             fmaf(e4.z, e4.z, e4.w * e4.w));
        x2p[i] = make_float2(-2.0f * e4.x, -2.0f * e4.z);
        y2p[i] = make_float2(-2.0f * e4.y, -2.0f * e4.w);
    }
    for (int i = L + tid; i < len4; i += TPB) {    // BIG pad -> tail-free loops
        s_c[i] = BIGF; s_x[i] = 0.0f; s_y[i] = 0.0f;
    }

    // ---- boundary_mask layout detection (first 4KB) ----
    unsigned int scan = 0;
    {
        const unsigned int* mw = (const unsigned int*)bmask;
        #pragma unroll
        for (int i = tid; i < 1024; i += TPB)
            scan |= (mw[i] & 0xFFFFFF00u);
    }
    const int mask_is_bytes = __syncthreads_or(scan != 0);  // also preload barrier

    // ---- deterministic compaction of this block's 512 verts (masked only) ----
    const int vbase = tile * TPB;                  // 512 verts per block
    const int midx0 = (b * Pn + p) * Vn + vbase + tid;
    bool m;
    if (mask_is_bytes) m = (((const unsigned char*)bmask)[midx0] != 0);
    else               m = (((const int*)bmask)[midx0] != 0);
    const unsigned int bal = __ballot_sync(0xffffffffu, m);
    if (lane31 == 0) s_wofs[wid + 1] = __popc(bal);
    __syncthreads();
    if (tid == 0) {
        s_wofs[0] = 0;
        #pragma unroll
        for (int i = 1; i <= 16; ++i) s_wofs[i] += s_wofs[i - 1];
    }
    __syncthreads();
    if (m) {
        const int pos = s_wofs[wid] + __popc(bal & ((1u << lane31) - 1u));
        s_vidx[pos] = (short)tid;                  // fixed tid order -> deterministic
    }
    const int NC = s_wofs[16];
    __syncthreads();

    const ulonglong2* pc  = (const ulonglong2*)s_c;
    const ulonglong2* pxv = (const ulonglong2*)s_x;
    const ulonglong2* pyv = (const ulonglong2*)s_y;
    const float* M = pm + p * 12;

    // ---- item loop: item = (chunk of 64 slots) x (edge quarter) ----
    const int nchunks = (NC + 63) >> 6;
    const int nitems  = nchunks << 2;
    for (int it = wid; it < nitems; it += 16) {
        const int chunk = it >> 2;
        const int seg   = it & 3;
        const int s0 = chunk * 64 + lane31;        // slots s0, s0+32

        // projections for the 2 owned slots
        int   slot[2];
        float px[2], py[2], ppv[2];
        unsigned long long pxx[2], pyy[2];
        #pragma unroll
        for (int j = 0; j < 2; ++j) {
            slot[j] = s0 + j * 32;
            float x = 0.0f, y = 0.0f, z = 0.0f;
            if (slot[j] < NC) {
                const int v = vbase + (int)s_vidx[slot[j]];
                const float* xv = xs + ((size_t)b * Vn + v) * 3;
                x = xv[0]; y = xv[1]; z = xv[2];
            }
            const float q0 = M[0] * x + M[1] * y + M[2]  * z + M[3];
            const float q1 = M[4] * x + M[5] * y + M[6]  * z + M[7];
            const float q2 = M[8] * x + M[9] * y + M[10] * z + M[11];
            px[j] = q0 / q2;
            py[j] = q1 / q2;
            ppv[j] = fmaf(px[j], px[j], py[j] * py[j]);
            pxx[j] = bcast2(px[j]);
            pyy[j] = bcast2(py[j]);
        }

        // edge loop over this quarter: 4 edges x 2 slots per iter
        const int i0 = S[seg] >> 2;
        const int i1 = S[seg + 1] >> 2;
        float ma[2], mb[2], mc[2], md[2];
        #pragma unroll
        for (int j = 0; j < 2; ++j) { ma[j]=BIGF; mb[j]=BIGF; mc[j]=BIGF; md[j]=BIGF; }

        if (i1 > i0) {
            ulonglong2 c4 = pc[i0], x4 = pxv[i0], y4 = pyv[i0];
            #pragma unroll 2
            for (int i = i0 + 1; i < i1; ++i) {
                const ulonglong2 cn = pc[i];
                const ulonglong2 xn = pxv[i];
                const ulonglong2 yn = pyv[i];
                #pragma unroll
                for (int j = 0; j < 2; ++j) {
                    edge2(ma[j], mb[j], pxx[j], pyy[j], x4.x, y4.x, c4.x);
                    edge2(mc[j], md[j], pxx[j], pyy[j], x4.y, y4.y, c4.y);
                }
                c4 = cn; x4 = xn; y4 = yn;
            }
            #pragma unroll
            for (int j = 0; j < 2; ++j) {
                edge2(ma[j], mb[j], pxx[j], pyy[j], x4.x, y4.x, c4.x);
                edge2(mc[j], md[j], pxx[j], pyy[j], x4.y, y4.y, c4.y);
            }
        }

        #pragma unroll
        for (int j = 0; j < 2; ++j) {
            if (slot[j] < NC) {
                s_e[seg][slot[j]] = fminf(fminf(ma[j], mb[j]), fminf(mc[j], md[j]));
                if (seg == 0) s_pp[slot[j]] = ppv[j];
            }
        }
    }
    __syncthreads();

    // ---- combine quarters per slot; weights all 1, count = NC ----
    float cs = 0.0f;
    if (tid < NC) {
        cs = fminf(fminf(s_e[0][tid], s_e[1][tid]),
                   fminf(s_e[2][tid], s_e[3][tid])) + s_pp[tid];
    }

    #pragma unroll
    for (int off = 16; off >= 1; off >>= 1)
        cs += __shfl_down_sync(0xffffffffu, cs, off);
    if (lane31 == 0) s_rs[wid] = cs;
    __syncthreads();

    if (tid == 0) {
        float ts = 0.0f;
        #pragma unroll
        for (int i = 0; i < TPB / 32; ++i) ts += s_rs[i];
        const int slotg = ((b * Pn + p) * TILES) + tile;
        g_part_sum[slotg] = ts;
        g_part_cnt[slotg] = (float)NC;
        __threadfence();
        unsigned int old = atomicAdd(&g_counter, 1u);
        s_last = (((old + 1u) & (CHAM_BLOCKS - 1u)) == 0u) ? 1 : 0;
    }
    __syncthreads();

    // ---- last block finalizes chamfer means ----
    if (s_last && tid < 32) {
        __threadfence();
        const int ln = tid;                      // ln = b*Pn + p
        float s = 0.0f, c = 0.0f;
        #pragma unroll
        for (int t = 0; t < TILES; ++t) {
            s += g_part_sum[ln * TILES + t];
            c += g_part_cnt[ln * TILES + t];
        }
        float ppj = s / fmaxf(c, 1.0f);
        #pragma unroll
        for (int off = 4; off >= 1; off >>= 1)
            ppj += __shfl_down_sync(0xffffffffu, ppj, off, 8);
        if ((ln & 7) == 0) out[ln >> 3] = ppj * (1.0f / Pn);
    }
}

// ---------------------------------------------------------------------------
extern "C" void kernel_launch(void* const* d_in, const int* in_sizes, int n_in,
                              void* d_out, int out_size)
{
    const float* xs    = (const float*)d_in[0];   // (4,2048,3)
    const float* pm    = (const float*)d_in[1];   // (8,3,4)
    const float* em    = (const float*)d_in[2];   // (4,8,2048,2)
    const int*   lens  = (const int*)  d_in[3];   // (4,8)
    const void*  bmask =               d_in[4];   // (4,8,2048) bool (auto-detected)
    const int*   faces = (const int*)  d_in[5];   // (4,4096,3)
    const float* tv    = (const float*)d_in[6];   // (4,)
    float* out = (float*)d_out;                   // [chamfer(4), vol_error(4)]

    fused_kernel<<<CHAM_BLOCKS + Bn, TPB>>>(xs, pm, em, lens, bmask, faces, tv, out);
}

// round 15
// speedup vs baseline: 1.4307x; 1.1064x over previous
#include <cuda_runtime.h>

#define Bn 4
#define Pn 8
#define Vn 2048
#define En 2048
#define Fn 4096
#define TILES 4
#define TPB 512              // 16 warps; items = (64-slot chunk) x (edge eighth)
#define NSEG 8
#define CHAM_BLOCKS (Bn * Pn * TILES)   // 128
#define EMAX 2052
#define BIGF 3.402823466e38f

__device__ float g_part_sum[CHAM_BLOCKS];
__device__ float g_part_cnt[CHAM_BLOCKS];
__device__ unsigned int g_counter;   // never reset; +CHAM_BLOCKS per launch

// ---------------------------------------------------------------------------
// packed fp32x2 helpers (sm_103a FFMA2)
// ---------------------------------------------------------------------------
__device__ __forceinline__ unsigned long long bcast2(float v) {
    unsigned long long r;
    asm("mov.b64 %0, {%1, %1};" : "=l"(r) : "f"(v));
    return r;
}

// d2[k] = px*x2[k] + py*y2[k] + c2[k]  for k=0,1 ; fold into mins
__device__ __forceinline__ void edge2(float& m0, float& m1,
                                      unsigned long long pxx, unsigned long long pyy,
                                      unsigned long long x2, unsigned long long y2,
                                      unsigned long long c2)
{
    float d0, d1;
    asm("{\n\t"
        ".reg .b64 t;\n\t"
        "fma.rn.f32x2 t, %2, %3, %4;\n\t"
        "fma.rn.f32x2 t, %5, %6, t;\n\t"
        "mov.b64 {%0, %1}, t;\n\t"
        "}"
        : "=f"(d0), "=f"(d1)
        : "l"(pyy), "l"(y2), "l"(c2), "l"(pxx), "l"(x2));
    m0 = fminf(m0, d0);
    m1 = fminf(m1, d1);
}

// ---------------------------------------------------------------------------
// Blocks [0,128): chamfer — 512 verts compacted to masked-only; work items =
// (64-slot chunk) x (edge eighth); projections hoisted to smem.
// Blocks [128,132): volume. One block/SM, single wave.
// ---------------------------------------------------------------------------
__global__ void __launch_bounds__(TPB)
fused_kernel(const float* __restrict__ xs,
             const float* __restrict__ pm,
             const float* __restrict__ em,
             const int*   __restrict__ lens,
             const void*  __restrict__ bmask,
             const int*   __restrict__ faces,
             const float* __restrict__ tv,
             float* __restrict__ out)
{
    const int bx  = blockIdx.x;
    const int tid = threadIdx.x;

    // =========================== VOLUME BLOCKS ============================
    if (bx >= CHAM_BLOCKS) {
        __shared__ double sred[TPB];
        const int b = bx - CHAM_BLOCKS;
        const float* base = xs + (size_t)b * Vn * 3;
        double acc = 0.0;
        for (int f = tid; f < Fn; f += TPB) {
            const int* fi = faces + ((size_t)b * Fn + f) * 3;
            const float* a0 = base + (size_t)fi[0] * 3;
            const float* a1 = base + (size_t)fi[1] * 3;
            const float* a2 = base + (size_t)fi[2] * 3;
            const float v0x = a0[0], v0y = a0[1], v0z = a0[2];
            const float v1x = a1[0], v1y = a1[1], v1z = a1[2];
            const float v2x = a2[0], v2y = a2[1], v2z = a2[2];
            const float cx = v0y * v1z - v0z * v1y;
            const float cy = v0z * v1x - v0x * v1z;
            const float cz = v0x * v1y - v0y * v1x;
            acc += (double)((cx * v2x + cy * v2y + cz * v2z) * (1.0f / 6.0f));
        }
        sred[tid] = acc;
        __syncthreads();
        #pragma unroll
        for (int s = TPB / 2; s >= 1; s >>= 1) {
            if (tid < s) sred[tid] += sred[tid + s];
            __syncthreads();
        }
        if (tid == 0) {
            float vols = fabsf((float)sred[0]);
            float d = vols - tv[b];
            out[4 + b] = d * d;
        }
        return;
    }

    // =========================== CHAMFER BLOCKS ===========================
    __shared__ __align__(16) float s_c[EMAX];
    __shared__ __align__(16) float s_x[EMAX];
    __shared__ __align__(16) float s_y[EMAX];
    __shared__ short  s_vidx[TPB];                 // compacted local vert ids
    __shared__ int    s_wofs[17];                  // warp prefix offsets
    __shared__ float2 s_pxy[TPB];                  // projected (px,py) per slot
    __shared__ float  s_pp[TPB];                   // |p|^2 per slot
    __shared__ float  s_e[NSEG][TPB];              // per-segment per-slot raw mins
    __shared__ float  s_rs[TPB / 32];
    __shared__ int    s_last;

    const int tile   = bx & (TILES - 1);
    const int p      = (bx >> 2) & (Pn - 1);
    const int b      = bx >> 5;
    const int lane31 = tid & 31;
    const int wid    = tid >> 5;

    const int L    = lens[b * Pn + p];
    const int len4 = (L + 3) & ~3;
    // 16B-aligned segment boundaries
    int S[NSEG + 1];
    S[0] = 0;
    #pragma unroll
    for (int k = 1; k < NSEG; ++k) S[k] = ((k * L / NSEG) + 3) & ~3;
    S[NSEG] = len4;

    // ---- preload + transform edge table ----
    const float4* embase4 = (const float4*)(em + ((size_t)(b * Pn + p)) * En * 2);
    float2* c2p = (float2*)s_c;
    float2* x2p = (float2*)s_x;
    float2* y2p = (float2*)s_y;
    #pragma unroll
    for (int i = tid; i < En / 2; i += TPB) {
        float4 e4 = embase4[i];                 // ex0, ey0, ex1, ey1
        c2p[i] = make_float2(fmaf(e4.x, e4.x, e4.y * e4.y),
                             fmaf(e4.z, e4.z, e4.w * e4.w));
        x2p[i] = make_float2(-2.0f * e4.x, -2.0f * e4.z);
        y2p[i] = make_float2(-2.0f * e4.y, -2.0f * e4.w);
    }
    for (int i = L + tid; i < len4; i += TPB) {    // BIG pad -> tail-free loops
        s_c[i] = BIGF; s_x[i] = 0.0f; s_y[i] = 0.0f;
    }

    // ---- boundary_mask layout detection (first 4KB) ----
    unsigned int scan = 0;
    {
        const unsigned int* mw = (const unsigned int*)bmask;
        #pragma unroll
        for (int i = tid; i < 1024; i += TPB)
            scan |= (mw[i] & 0xFFFFFF00u);
    }
    const int mask_is_bytes = __syncthreads_or(scan != 0);  // also preload barrier

    // ---- deterministic compaction of this block's 512 verts (masked only) ----
    const int vbase = tile * TPB;                  // 512 verts per block
    const int midx0 = (b * Pn + p) * Vn + vbase + tid;
    bool m;
    if (mask_is_bytes) m = (((const unsigned char*)bmask)[midx0] != 0);
    else               m = (((const int*)bmask)[midx0] != 0);
    const unsigned int bal = __ballot_sync(0xffffffffu, m);
    if (lane31 == 0) s_wofs[wid + 1] = __popc(bal);
    __syncthreads();
    if (tid == 0) {
        s_wofs[0] = 0;
        #pragma unroll
        for (int i = 1; i <= 16; ++i) s_wofs[i] += s_wofs[i - 1];
    }
    __syncthreads();
    if (m) {
        const int pos = s_wofs[wid] + __popc(bal & ((1u << lane31) - 1u));
        s_vidx[pos] = (short)tid;                  // fixed tid order -> deterministic
    }
    const int NC = s_wofs[16];
    __syncthreads();

    // ---- hoisted projections: one thread per compacted slot ----
    {
        const float* M = pm + p * 12;
        if (tid < NC) {
            const int v = vbase + (int)s_vidx[tid];
            const float* xv = xs + ((size_t)b * Vn + v) * 3;
            const float x = xv[0], y = xv[1], z = xv[2];
            const float q0 = M[0] * x + M[1] * y + M[2]  * z + M[3];
            const float q1 = M[4] * x + M[5] * y + M[6]  * z + M[7];
            const float q2 = M[8] * x + M[9] * y + M[10] * z + M[11];
            const float px = q0 / q2;
            const float py = q1 / q2;
            s_pxy[tid] = make_float2(px, py);
            s_pp[tid]  = fmaf(px, px, py * py);
        }
    }
    __syncthreads();

    const ulonglong2* pc  = (const ulonglong2*)s_c;
    const ulonglong2* pxv = (const ulonglong2*)s_x;
    const ulonglong2* pyv = (const ulonglong2*)s_y;

    // ---- item loop: item = (chunk of 64 slots) x (edge eighth) ----
    const int nchunks = (NC + 63) >> 6;
    const int nitems  = nchunks * NSEG;
    for (int it = wid; it < nitems; it += 16) {
        const int chunk = it >> 3;
        const int seg   = it & (NSEG - 1);
        const int s0 = chunk * 64 + lane31;        // slots s0, s0+32

        int   slot[2];
        unsigned long long pxx[2], pyy[2];
        #pragma unroll
        for (int j = 0; j < 2; ++j) {
            slot[j] = s0 + j * 32;
            float2 pxy = make_float2(0.0f, 0.0f);
            if (slot[j] < NC) pxy = s_pxy[slot[j]];
            pxx[j] = bcast2(pxy.x);
            pyy[j] = bcast2(pxy.y);
        }

        const int i0 = S[seg] >> 2;
        const int i1 = S[seg + 1] >> 2;
        float ma[2], mb[2], mc[2], md[2];
        #pragma unroll
        for (int j = 0; j < 2; ++j) { ma[j]=BIGF; mb[j]=BIGF; mc[j]=BIGF; md[j]=BIGF; }

        if (i1 > i0) {
            ulonglong2 c4 = pc[i0], x4 = pxv[i0], y4 = pyv[i0];
            #pragma unroll 2
            for (int i = i0 + 1; i < i1; ++i) {
                const ulonglong2 cn = pc[i];
                const ulonglong2 xn = pxv[i];
                const ulonglong2 yn = pyv[i];
                #pragma unroll
                for (int j = 0; j < 2; ++j) {
                    edge2(ma[j], mb[j], pxx[j], pyy[j], x4.x, y4.x, c4.x);
                    edge2(mc[j], md[j], pxx[j], pyy[j], x4.y, y4.y, c4.y);
                }
                c4 = cn; x4 = xn; y4 = yn;
            }
            #pragma unroll
            for (int j = 0; j < 2; ++j) {
                edge2(ma[j], mb[j], pxx[j], pyy[j], x4.x, y4.x, c4.x);
                edge2(mc[j], md[j], pxx[j], pyy[j], x4.y, y4.y, c4.y);
            }
        }

        #pragma unroll
        for (int j = 0; j < 2; ++j) {
            if (slot[j] < NC)
                s_e[seg][slot[j]] = fminf(fminf(ma[j], mb[j]), fminf(mc[j], md[j]));
        }
    }
    __syncthreads();

    // ---- combine segments per slot; weights all 1, count = NC ----
    float cs = 0.0f;
    if (tid < NC) {
        float mn = s_e[0][tid];
        #pragma unroll
        for (int k = 1; k < NSEG; ++k) mn = fminf(mn, s_e[k][tid]);
        cs = mn + s_pp[tid];
    }

    #pragma unroll
    for (int off = 16; off >= 1; off >>= 1)
        cs += __shfl_down_sync(0xffffffffu, cs, off);
    if (lane31 == 0) s_rs[wid] = cs;
    __syncthreads();

    if (tid == 0) {
        float ts = 0.0f;
        #pragma unroll
        for (int i = 0; i < TPB / 32; ++i) ts += s_rs[i];
        const int slotg = ((b * Pn + p) * TILES) + tile;
        g_part_sum[slotg] = ts;
        g_part_cnt[slotg] = (float)NC;
        __threadfence();
        unsigned int old = atomicAdd(&g_counter, 1u);
        s_last = (((old + 1u) & (CHAM_BLOCKS - 1u)) == 0u) ? 1 : 0;
    }
    __syncthreads();

    // ---- last block finalizes chamfer means ----
    if (s_last && tid < 32) {
        __threadfence();
        const int ln = tid;                      // ln = b*Pn + p
        float s = 0.0f, c = 0.0f;
        #pragma unroll
        for (int t = 0; t < TILES; ++t) {
            s += g_part_sum[ln * TILES + t];
            c += g_part_cnt[ln * TILES + t];
        }
        float ppj = s / fmaxf(c, 1.0f);
        #pragma unroll
        for (int off = 4; off >= 1; off >>= 1)
            ppj += __shfl_down_sync(0xffffffffu, ppj, off, 8);
        if ((ln & 7) == 0) out[ln >> 3] = ppj * (1.0f / Pn);
    }
}

// ---------------------------------------------------------------------------
extern "C" void kernel_launch(void* const* d_in, const int* in_sizes, int n_in,
                              void* d_out, int out_size)
{
    const float* xs    = (const float*)d_in[0];   // (4,2048,3)
    const float* pm    = (const float*)d_in[1];   // (8,3,4)
    const float* em    = (const float*)d_in[2];   // (4,8,2048,2)
    const int*   lens  = (const int*)  d_in[3];   // (4,8)
    const void*  bmask =               d_in[4];   // (4,8,2048) bool (auto-detected)
    const int*   faces = (const int*)  d_in[5];   // (4,4096,3)
    const float* tv    = (const float*)d_in[6];   // (4,)
    float* out = (float*)d_out;                   // [chamfer(4), vol_error(4)]

    fused_kernel<<<CHAM_BLOCKS + Bn, TPB>>>(xs, pm, em, lens, bmask, faces, tv, out);
}